// round 2
// baseline (speedup 1.0000x reference)
#include <cuda_runtime.h>
#include <math.h>

#define NBAGS 65536
#define EPSF 1e-7f

// ---- scratch (no cudaMalloc allowed) ----
__device__ float         g_pos_seg[NBAGS];
__device__ unsigned char g_neg_present[NBAGS];
__device__ unsigned char g_pos_present[NBAGS];
// 0: neg_sum, 1: num_neg_bags, 2: num_pos_bags, 3: pos_per_bag_sum
__device__ float         g_accum[4];

__global__ void mil_init_kernel() {
    int i = blockIdx.x * blockDim.x + threadIdx.x;
    if (i < NBAGS) {
        g_pos_seg[i] = 0.0f;
        g_neg_present[i] = 0;
        g_pos_present[i] = 0;
    }
    if (i < 4) g_accum[i] = 0.0f;
}

__device__ __forceinline__ void mil_process(float p, int l, int b, float& local_neg) {
    float ln = logf(1.0f - p + EPSF);
    if (l == 0) {
        local_neg += ln;
        g_neg_present[b] = 1;            // benign race: everyone writes 1
    } else {
        atomicAdd(&g_pos_seg[b], ln);
        g_pos_present[b] = 1;
    }
}

__global__ void __launch_bounds__(256) mil_main_kernel(
        const float4* __restrict__ p4,
        const int4* __restrict__ l4,
        const int4* __restrict__ b4,
        int n4, int n_total,
        const float* __restrict__ p_s,
        const int* __restrict__ l_s,
        const int* __restrict__ b_s) {
    int stride = gridDim.x * blockDim.x;
    float local = 0.0f;

    for (int i = blockIdx.x * blockDim.x + threadIdx.x; i < n4; i += stride) {
        float4 p = p4[i];
        int4   l = l4[i];
        int4   b = b4[i];
        mil_process(p.x, l.x, b.x, local);
        mil_process(p.y, l.y, b.y, local);
        mil_process(p.z, l.z, b.z, local);
        mil_process(p.w, l.w, b.w, local);
    }
    // scalar tail (N % 4 != 0): distribute across threads
    for (int j = n4 * 4 + blockIdx.x * blockDim.x + threadIdx.x;
         j < n_total; j += stride) {
        mil_process(p_s[j], l_s[j], b_s[j], local);
    }

    // block reduction of local neg-sum -> 1 atomic per block
    __shared__ float warp_sums[8];
    int lane = threadIdx.x & 31;
    int wid  = threadIdx.x >> 5;
    #pragma unroll
    for (int off = 16; off > 0; off >>= 1)
        local += __shfl_down_sync(0xFFFFFFFFu, local, off);
    if (lane == 0) warp_sums[wid] = local;
    __syncthreads();
    if (wid == 0) {
        float v = (lane < 8) ? warp_sums[lane] : 0.0f;
        #pragma unroll
        for (int off = 4; off > 0; off >>= 1)
            v += __shfl_down_sync(0xFFFFFFFFu, v, off);
        if (lane == 0) atomicAdd(&g_accum[0], v);
    }
}

__global__ void __launch_bounds__(256) mil_bag_kernel() {
    int i = blockIdx.x * blockDim.x + threadIdx.x;
    float nneg = 0.0f, npos = 0.0f, psum = 0.0f;
    if (i < NBAGS) {
        if (g_neg_present[i]) nneg = 1.0f;
        if (g_pos_present[i]) {
            npos = 1.0f;
            float s = g_pos_seg[i];
            float v = fminf(expf(s), 1.0f);
            psum = logf(1.0f - v + EPSF);
        }
    }
    __shared__ float sh[3][8];
    int lane = threadIdx.x & 31;
    int wid  = threadIdx.x >> 5;
    #pragma unroll
    for (int off = 16; off > 0; off >>= 1) {
        nneg += __shfl_down_sync(0xFFFFFFFFu, nneg, off);
        npos += __shfl_down_sync(0xFFFFFFFFu, npos, off);
        psum += __shfl_down_sync(0xFFFFFFFFu, psum, off);
    }
    if (lane == 0) { sh[0][wid] = nneg; sh[1][wid] = npos; sh[2][wid] = psum; }
    __syncthreads();
    if (wid == 0) {
        float a = (lane < 8) ? sh[0][lane] : 0.0f;
        float b = (lane < 8) ? sh[1][lane] : 0.0f;
        float c = (lane < 8) ? sh[2][lane] : 0.0f;
        #pragma unroll
        for (int off = 4; off > 0; off >>= 1) {
            a += __shfl_down_sync(0xFFFFFFFFu, a, off);
            b += __shfl_down_sync(0xFFFFFFFFu, b, off);
            c += __shfl_down_sync(0xFFFFFFFFu, c, off);
        }
        if (lane == 0) {
            atomicAdd(&g_accum[1], a);
            atomicAdd(&g_accum[2], b);
            atomicAdd(&g_accum[3], c);
        }
    }
}

__global__ void mil_final_kernel(float* out) {
    float neg_sum = g_accum[0];
    float nn      = g_accum[1];
    float np      = g_accum[2];
    float ps      = g_accum[3];
    float neg_loss = (nn > 0.0f) ? (-(1.0f * neg_sum) / fmaxf(nn, 1.0f)) : 0.0f;
    float pos_loss = (np > 0.0f) ? (-(1.0f * ps)      / fmaxf(np, 1.0f)) : 0.0f;
    out[0] = neg_loss + pos_loss;
}

extern "C" void kernel_launch(void* const* d_in, const int* in_sizes, int n_in,
                              void* d_out, int out_size) {
    const float* probas  = (const float*)d_in[0];
    const int*   labels  = (const int*)d_in[1];
    const int*   bag_ids = (const int*)d_in[2];
    float*       out     = (float*)d_out;
    int n  = in_sizes[0];
    int n4 = n >> 2;

    mil_init_kernel<<<(NBAGS + 255) / 256, 256>>>();

    // enough blocks to cover n4 in one grid-stride trip on a full chip,
    // capped so each block does a decent chunk (>= ~8 iterations)
    int blocks = (n4 + 255) / 256;
    const int max_blocks = 148 * 16;   // ~16 blocks/SM cap
    if (blocks > max_blocks) blocks = max_blocks;
    if (blocks < 1) blocks = 1;
    mil_main_kernel<<<blocks, 256>>>((const float4*)probas, (const int4*)labels,
                                     (const int4*)bag_ids, n4, n,
                                     probas, labels, bag_ids);

    mil_bag_kernel<<<NBAGS / 256, 256>>>();

    mil_final_kernel<<<1, 1>>>(out);
}

// round 3
// speedup vs baseline: 2.9381x; 2.9381x over previous
#include <cuda_runtime.h>
#include <math.h>

#define NBAGS 65536
#define EPSF 1e-7f

// packed word per bag:
//   [0:44)  pos sum of log(1-p+eps), fixed point 2^-22, mod 2^44
//   [44:54) pos count (with borrow from sum field; reconstructed at decode)
//   [54:64) neg count (presence)
__device__ unsigned long long g_packed[NBAGS];
// 0: neg_sum, 1: num_neg_bags, 2: num_pos_bags, 3: pos_per_bag_sum
__device__ float        g_accum[4];
__device__ unsigned int g_done;

#define FIX_SCALE 4194304.0f          /* 2^22 */
#define INV_FIX   2.3841858e-7f       /* 2^-22 */
#define MASK44    ((1ULL << 44) - 1)
#define MASK54    ((1ULL << 54) - 1)

__global__ void mil_init_kernel() {
    int i = blockIdx.x * blockDim.x + threadIdx.x;
    if (i < NBAGS) g_packed[i] = 0ULL;
    if (i < 4)     g_accum[i] = 0.0f;
    if (i == 4)    g_done = 0u;
}

__device__ __forceinline__ void mil_process(float p, int l, int b, float& local_neg) {
    float ln = __logf(1.0f - p + EPSF);
    bool is_neg = (l == 0);
    long long fx = __float2ll_rn(ln * FIX_SCALE);
    unsigned long long add = is_neg
        ? (1ULL << 54)
        : ((1ULL << 44) + ((unsigned long long)fx & MASK44));
    atomicAdd(&g_packed[b], add);      // return unused -> RED.64
    local_neg += is_neg ? ln : 0.0f;
}

__global__ void __launch_bounds__(256) mil_main_kernel(
        const float4* __restrict__ p4,
        const int4* __restrict__ l4,
        const int4* __restrict__ b4,
        int n4, int n_total,
        const float* __restrict__ p_s,
        const int* __restrict__ l_s,
        const int* __restrict__ b_s) {
    int stride = gridDim.x * blockDim.x;
    float local = 0.0f;

    for (int i = blockIdx.x * blockDim.x + threadIdx.x; i < n4; i += stride) {
        float4 p = p4[i];
        int4   l = l4[i];
        int4   b = b4[i];
        mil_process(p.x, l.x, b.x, local);
        mil_process(p.y, l.y, b.y, local);
        mil_process(p.z, l.z, b.z, local);
        mil_process(p.w, l.w, b.w, local);
    }
    for (int j = n4 * 4 + blockIdx.x * blockDim.x + threadIdx.x;
         j < n_total; j += stride) {
        mil_process(p_s[j], l_s[j], b_s[j], local);
    }

    __shared__ float warp_sums[8];
    int lane = threadIdx.x & 31;
    int wid  = threadIdx.x >> 5;
    #pragma unroll
    for (int off = 16; off > 0; off >>= 1)
        local += __shfl_down_sync(0xFFFFFFFFu, local, off);
    if (lane == 0) warp_sums[wid] = local;
    __syncthreads();
    if (wid == 0) {
        float v = (lane < 8) ? warp_sums[lane] : 0.0f;
        #pragma unroll
        for (int off = 4; off > 0; off >>= 1)
            v += __shfl_down_sync(0xFFFFFFFFu, v, off);
        if (lane == 0) atomicAdd(&g_accum[0], v);
    }
}

// bag decode + partial reduce + (last block) final scalar
__global__ void __launch_bounds__(256) mil_bag_final_kernel(float* out) {
    int i = blockIdx.x * blockDim.x + threadIdx.x;
    float nneg = 0.0f, npos = 0.0f, psum = 0.0f;
    if (i < NBAGS) {
        unsigned long long W = g_packed[i];
        unsigned int negc = (unsigned int)(W >> 54);
        unsigned long long pos_part = W & MASK54;
        if (negc) nneg = 1.0f;
        if (pos_part != 0ULL) {
            npos = 1.0f;
            unsigned long long low44 = pos_part & MASK44;
            long long s_fixed = (low44 >= (1ULL << 43))
                ? (long long)low44 - (1LL << 44)
                : (long long)low44;
            float seg = (float)s_fixed * INV_FIX;
            float v = fminf(expf(seg), 1.0f);
            psum = logf(1.0f - v + EPSF);
        }
    }
    __shared__ float sh[3][8];
    int lane = threadIdx.x & 31;
    int wid  = threadIdx.x >> 5;
    #pragma unroll
    for (int off = 16; off > 0; off >>= 1) {
        nneg += __shfl_down_sync(0xFFFFFFFFu, nneg, off);
        npos += __shfl_down_sync(0xFFFFFFFFu, npos, off);
        psum += __shfl_down_sync(0xFFFFFFFFu, psum, off);
    }
    if (lane == 0) { sh[0][wid] = nneg; sh[1][wid] = npos; sh[2][wid] = psum; }
    __syncthreads();
    bool last = false;
    if (wid == 0) {
        float a = (lane < 8) ? sh[0][lane] : 0.0f;
        float b = (lane < 8) ? sh[1][lane] : 0.0f;
        float c = (lane < 8) ? sh[2][lane] : 0.0f;
        #pragma unroll
        for (int off = 4; off > 0; off >>= 1) {
            a += __shfl_down_sync(0xFFFFFFFFu, a, off);
            b += __shfl_down_sync(0xFFFFFFFFu, b, off);
            c += __shfl_down_sync(0xFFFFFFFFu, c, off);
        }
        if (lane == 0) {
            atomicAdd(&g_accum[1], a);
            atomicAdd(&g_accum[2], b);
            atomicAdd(&g_accum[3], c);
            __threadfence();
            unsigned int t = atomicAdd(&g_done, 1u);
            last = (t == gridDim.x - 1);
        }
    }
    if (last) {
        float neg_sum = g_accum[0];
        float nn      = g_accum[1];
        float np      = g_accum[2];
        float ps      = g_accum[3];
        float neg_loss = (nn > 0.0f) ? (-neg_sum / fmaxf(nn, 1.0f)) : 0.0f;
        float pos_loss = (np > 0.0f) ? (-ps      / fmaxf(np, 1.0f)) : 0.0f;
        out[0] = neg_loss + pos_loss;
    }
}

extern "C" void kernel_launch(void* const* d_in, const int* in_sizes, int n_in,
                              void* d_out, int out_size) {
    const float* probas  = (const float*)d_in[0];
    const int*   labels  = (const int*)d_in[1];
    const int*   bag_ids = (const int*)d_in[2];
    float*       out     = (float*)d_out;
    int n  = in_sizes[0];
    int n4 = n >> 2;

    mil_init_kernel<<<(NBAGS + 255) / 256, 256>>>();

    int blocks = (n4 + 255) / 256;
    const int max_blocks = 148 * 16;
    if (blocks > max_blocks) blocks = max_blocks;
    if (blocks < 1) blocks = 1;
    mil_main_kernel<<<blocks, 256>>>((const float4*)probas, (const int4*)labels,
                                     (const int4*)bag_ids, n4, n,
                                     probas, labels, bag_ids);

    mil_bag_final_kernel<<<NBAGS / 256, 256>>>(out);
}